// round 1
// baseline (speedup 1.0000x reference)
#include <cuda_runtime.h>
#include <math.h>

#define BATCH 4
#define NSEQ 2048
#define DIM 512
#define HEADS 8
#define DHEAD 64
#define BH (BATCH*HEADS)      /* 32  */
#define ROWS (BATCH*NSEQ)     /* 8192 */
#define NTILES (NSEQ/64)      /* 32  */
#define MASK_FILL 1e-8f

// ---------------- scratch (no allocations allowed) ----------------
__device__ float g_hn[ROWS * DIM];                      // 16 MB LayerNorm output
__device__ float g_q[BH * NSEQ * DHEAD];                // 16 MB
__device__ float g_k[BH * NSEQ * DHEAD];                // 16 MB
__device__ float g_v[BH * NSEQ * DHEAD];                // 16 MB
__device__ float g_vsuf[BH * (NTILES + 1) * DHEAD];     // V suffix column sums

// ---------------- 1) LayerNorm ----------------
__global__ __launch_bounds__(128)
void ln_kernel(const float* __restrict__ x,
               const float* __restrict__ gamma,
               const float* __restrict__ beta) {
    int row = blockIdx.x;
    int tid = threadIdx.x;                 // 128 threads * float4 = 512 elems
    const float4* xr = (const float4*)(x + (size_t)row * DIM);
    float4 v = xr[tid];
    float s  = v.x + v.y + v.z + v.w;
    float s2 = v.x*v.x + v.y*v.y + v.z*v.z + v.w*v.w;
    #pragma unroll
    for (int o = 16; o > 0; o >>= 1) {
        s  += __shfl_xor_sync(0xffffffffu, s,  o);
        s2 += __shfl_xor_sync(0xffffffffu, s2, o);
    }
    __shared__ float ss[4], ss2[4];
    int w = tid >> 5;
    if ((tid & 31) == 0) { ss[w] = s; ss2[w] = s2; }
    __syncthreads();
    s  = ss[0] + ss[1] + ss[2] + ss[3];
    s2 = ss2[0] + ss2[1] + ss2[2] + ss2[3];
    float mean = s * (1.0f / DIM);
    float var  = s2 * (1.0f / DIM) - mean * mean;
    float inv  = rsqrtf(var + 1e-5f);
    float4 g  = ((const float4*)gamma)[tid];
    float4 bt = ((const float4*)beta)[tid];
    float4 o;
    o.x = (v.x - mean) * inv * g.x + bt.x;
    o.y = (v.y - mean) * inv * g.y + bt.y;
    o.z = (v.z - mean) * inv * g.z + bt.z;
    o.w = (v.w - mean) * inv * g.w + bt.w;
    ((float4*)(g_hn + (size_t)row * DIM))[tid] = o;
}

// ---------------- 2) QKV GEMM:  C[m,n] = sum_k hn[m,k] * W[n,k] ----------------
// 64x64 tile, K-step 16, 256 threads, 4x4 micro-tile. Epilogue scatters into
// [B,H,N,D] q/k/v layouts.
#define GTK 16
__global__ __launch_bounds__(256)
void qkv_gemm(const float* __restrict__ W) {
    __shared__ float As[GTK][68];   // transposed [k][m]
    __shared__ float Bs[GTK][68];   // transposed [k][n]
    int nb = blockIdx.x * 64;       // 0..1535
    int mb = blockIdx.y * 64;       // 0..8191
    int tid = threadIdx.x;
    int tx = tid & 15, ty = tid >> 4;
    int lr = tid >> 2;              // 0..63
    int lk = (tid & 3) * 4;         // 0,4,8,12
    const float* A = g_hn;
    float acc[4][4];
    #pragma unroll
    for (int i = 0; i < 4; i++)
        #pragma unroll
        for (int j = 0; j < 4; j++) acc[i][j] = 0.f;

    for (int k0 = 0; k0 < DIM; k0 += GTK) {
        float4 av = *(const float4*)&A[(size_t)(mb + lr) * DIM + k0 + lk];
        float4 bv = *(const float4*)&W[(size_t)(nb + lr) * DIM + k0 + lk];
        As[lk+0][lr] = av.x; As[lk+1][lr] = av.y; As[lk+2][lr] = av.z; As[lk+3][lr] = av.w;
        Bs[lk+0][lr] = bv.x; Bs[lk+1][lr] = bv.y; Bs[lk+2][lr] = bv.z; Bs[lk+3][lr] = bv.w;
        __syncthreads();
        #pragma unroll
        for (int kk = 0; kk < GTK; kk++) {
            float4 a4 = *(const float4*)&As[kk][ty * 4];
            float4 b4 = *(const float4*)&Bs[kk][tx * 4];
            float a[4] = {a4.x, a4.y, a4.z, a4.w};
            float b[4] = {b4.x, b4.y, b4.z, b4.w};
            #pragma unroll
            for (int i = 0; i < 4; i++)
                #pragma unroll
                for (int j = 0; j < 4; j++)
                    acc[i][j] += a[i] * b[j];
        }
        __syncthreads();
    }
    // epilogue: n = nb + tx*4 + j; head constant per block (nb is 64-aligned)
    int chunk = nb / 512;           // 0=q 1=k 2=v
    int head  = (nb % 512) >> 6;    // constant for the whole block
    float* dst = (chunk == 0) ? g_q : (chunk == 1) ? g_k : g_v;
    #pragma unroll
    for (int i = 0; i < 4; i++) {
        int m  = mb + ty * 4 + i;
        int bi = m / NSEQ;
        int nr = m % NSEQ;
        size_t ob = (((size_t)(bi * HEADS + head)) * NSEQ + nr) * DHEAD + tx * 4;
        *(float4*)&dst[ob] = make_float4(acc[i][0], acc[i][1], acc[i][2], acc[i][3]);
    }
}

// ---------------- 3) V suffix column sums per 64-row tile ----------------
__global__ __launch_bounds__(64)
void vsuf_kernel() {
    int bh = blockIdx.x;
    int d  = threadIdx.x;           // 0..63
    const float* V = g_v + (size_t)bh * NSEQ * DHEAD;
    float acc = 0.f;
    g_vsuf[((size_t)bh * (NTILES + 1) + NTILES) * DHEAD + d] = 0.f;
    for (int t = NTILES - 1; t >= 0; t--) {
        #pragma unroll 4
        for (int r = 63; r >= 0; r--)
            acc += V[(size_t)(t * 64 + r) * DHEAD + d];
        g_vsuf[((size_t)bh * (NTILES + 1) + t) * DHEAD + d] = acc;
    }
}

// ---------------- 4) attention ----------------
// Block: 64 query rows of one (b,h). 256 threads, 4x4 micro-tiles.
// Online softmax over key tiles kt<=qt; uniform masked region folded in as a
// rank-1 update using V suffix sums (exact: masked logits are all 1e-8).
#define TQ 64
#define TKY 64
#define SSTR 68   /* stride keeps float4 alignment (68*4=272=17*16) */

__global__ __launch_bounds__(256, 2)
void attn_kernel(float* __restrict__ out) {
    extern __shared__ float sm[];
    float* Qs = sm;                    // [64][SSTR], natural [r][d]
    float* KV = sm + TQ * SSTR;        // K transposed [d][c]  /  V natural [c][d]
    float* Ps = sm + 2 * TQ * SSTR;    // natural [r][c]

    int qt = blockIdx.x;               // query tile 0..31
    int bh = blockIdx.y;               // 0..31
    int b  = bh / HEADS;
    int h  = bh % HEADS;
    size_t base = (size_t)bh * NSEQ * DHEAD;
    const float* Q = g_q + base;
    const float* K = g_k + base;
    const float* V = g_v + base;

    int tid = threadIdx.x;
    int tx = tid & 15, ty = tid >> 4;
    int r0 = ty * 4, c0 = tx * 4;
    int lc = tid >> 2;                 // loader row 0..63
    int ld = (tid & 3) * 4;            // loader dim 0,4,8,12

    // load Q tile (natural layout)
    #pragma unroll
    for (int ch = 0; ch < 4; ch++) {
        int d = ld + ch * 16;
        float4 qv = *(const float4*)&Q[(size_t)(qt * TQ + lc) * DHEAD + d];
        *(float4*)&Qs[lc * SSTR + d] = qv;
    }

    float m[4], l[4], o[4][4];
    #pragma unroll
    for (int i = 0; i < 4; i++) {
        m[i] = -1e30f; l[i] = 0.f;
        #pragma unroll
        for (int j = 0; j < 4; j++) o[i][j] = 0.f;
    }

    for (int kt = 0; kt <= qt; kt++) {
        __syncthreads();   // KV/Ps free from previous iteration; Qs visible (iter 0)
        // load K tile transposed: KV[d][c]
        #pragma unroll
        for (int ch = 0; ch < 4; ch++) {
            int d = ld + ch * 16;
            float4 kv = *(const float4*)&K[(size_t)(kt * TKY + lc) * DHEAD + d];
            KV[(d+0) * SSTR + lc] = kv.x;
            KV[(d+1) * SSTR + lc] = kv.y;
            KV[(d+2) * SSTR + lc] = kv.z;
            KV[(d+3) * SSTR + lc] = kv.w;
        }
        __syncthreads();

        // S = Q K^T
        float s[4][4];
        #pragma unroll
        for (int i = 0; i < 4; i++)
            #pragma unroll
            for (int j = 0; j < 4; j++) s[i][j] = 0.f;
        #pragma unroll
        for (int dd = 0; dd < DHEAD; dd++) {
            float qv[4];
            #pragma unroll
            for (int i = 0; i < 4; i++) qv[i] = Qs[(r0 + i) * SSTR + dd];
            float4 k4 = *(const float4*)&KV[dd * SSTR + c0];
            float kv[4] = {k4.x, k4.y, k4.z, k4.w};
            #pragma unroll
            for (int i = 0; i < 4; i++)
                #pragma unroll
                for (int j = 0; j < 4; j++)
                    s[i][j] += qv[i] * kv[j];
        }
        // mask only matters on the diagonal tile
        if (kt == qt) {
            #pragma unroll
            for (int i = 0; i < 4; i++)
                #pragma unroll
                for (int j = 0; j < 4; j++)
                    if (c0 + j > r0 + i) s[i][j] = MASK_FILL;
        }
        // online softmax (rows spread over 16 tx lanes)
        float scale[4];
        #pragma unroll
        for (int i = 0; i < 4; i++) {
            float mx = fmaxf(fmaxf(s[i][0], s[i][1]), fmaxf(s[i][2], s[i][3]));
            #pragma unroll
            for (int off = 8; off > 0; off >>= 1)
                mx = fmaxf(mx, __shfl_xor_sync(0xffffffffu, mx, off));
            float mn = fmaxf(m[i], mx);
            scale[i] = __expf(m[i] - mn);
            m[i] = mn;
            float su = 0.f;
            #pragma unroll
            for (int j = 0; j < 4; j++) {
                s[i][j] = __expf(s[i][j] - mn);
                su += s[i][j];
            }
            #pragma unroll
            for (int off = 8; off > 0; off >>= 1)
                su += __shfl_xor_sync(0xffffffffu, su, off);
            l[i] = l[i] * scale[i] + su;
        }
        // stash P
        #pragma unroll
        for (int i = 0; i < 4; i++)
            *(float4*)&Ps[(r0 + i) * SSTR + c0] =
                make_float4(s[i][0], s[i][1], s[i][2], s[i][3]);
        __syncthreads();   // Ps visible; KV free
        // load V tile natural: KV[c][d]
        #pragma unroll
        for (int ch = 0; ch < 4; ch++) {
            int d = ld + ch * 16;
            float4 vv = *(const float4*)&V[(size_t)(kt * TKY + lc) * DHEAD + d];
            *(float4*)&KV[lc * SSTR + d] = vv;
        }
        __syncthreads();
        // O = O*scale + P V
        #pragma unroll
        for (int i = 0; i < 4; i++)
            #pragma unroll
            for (int j = 0; j < 4; j++)
                o[i][j] *= scale[i];
        #pragma unroll
        for (int cc = 0; cc < TKY; cc++) {
            float pv[4];
            #pragma unroll
            for (int i = 0; i < 4; i++) pv[i] = Ps[(r0 + i) * SSTR + cc];
            float4 v4 = *(const float4*)&KV[cc * SSTR + c0];
            float vv[4] = {v4.x, v4.y, v4.z, v4.w};
            #pragma unroll
            for (int i = 0; i < 4; i++)
                #pragma unroll
                for (int j = 0; j < 4; j++)
                    o[i][j] += pv[i] * vv[j];
        }
    }

    // uniform masked region (keys > qt tile): all logits == MASK_FILL -> rank-1
    int cnt = NSEQ - (qt + 1) * TKY;
    if (cnt > 0) {
        const float* vs = g_vsuf + ((size_t)bh * (NTILES + 1) + (qt + 1)) * DHEAD;
        float vsv[4];
        #pragma unroll
        for (int j = 0; j < 4; j++) vsv[j] = vs[c0 + j];
        #pragma unroll
        for (int i = 0; i < 4; i++) {
            float mn  = fmaxf(m[i], MASK_FILL);
            float scl = __expf(m[i] - mn);
            float e   = __expf(MASK_FILL - mn);
            l[i] = l[i] * scl + e * (float)cnt;
            m[i] = mn;
            #pragma unroll
            for (int j = 0; j < 4; j++)
                o[i][j] = o[i][j] * scl + e * vsv[j];
        }
    }

    // normalize and write: out[b][qrow][h*64 + d]
    #pragma unroll
    for (int i = 0; i < 4; i++) {
        float invl = 1.0f / l[i];
        int grow = qt * TQ + r0 + i;
        size_t ob = ((size_t)b * NSEQ + grow) * DIM + h * DHEAD + c0;
        *(float4*)&out[ob] = make_float4(o[i][0] * invl, o[i][1] * invl,
                                         o[i][2] * invl, o[i][3] * invl);
    }
}

// ---------------- launch ----------------
extern "C" void kernel_launch(void* const* d_in, const int* in_sizes, int n_in,
                              void* d_out, int out_size) {
    const float* x     = (const float*)d_in[0];
    const float* gamma = (const float*)d_in[1];
    const float* beta  = (const float*)d_in[2];
    const float* w_qkv = (const float*)d_in[3];
    // d_in[4] = mask (tril bool) — structurally causal; not needed at runtime.
    float* out = (float*)d_out;

    ln_kernel<<<ROWS, 128>>>(x, gamma, beta);
    qkv_gemm<<<dim3(1536 / 64, ROWS / 64), 256>>>(w_qkv);
    vsuf_kernel<<<BH, 64>>>();

    int smem = 3 * TQ * SSTR * (int)sizeof(float);   // 52224 B
    cudaFuncSetAttribute(attn_kernel, cudaFuncAttributeMaxDynamicSharedMemorySize, smem);
    attn_kernel<<<dim3(NTILES, BH), 256, smem>>>(out);
}

// round 6
// speedup vs baseline: 1.6749x; 1.6749x over previous
#include <cuda_runtime.h>
#include <math.h>
#include <stdint.h>

#define BATCH 4
#define NSEQ 2048
#define DIM 512
#define HEADS 8
#define DHEAD 64
#define BH (BATCH*HEADS)      /* 32  */
#define ROWS (BATCH*NSEQ)     /* 8192 */
#define NT64 32               /* 64-row tiles (vsuf granularity) */
#define NQT 16                /* 128-row q tiles */
#define MASK_FILL 1e-8f

// ---------------- scratch ----------------
__device__ float g_hn [ROWS * DIM];
__device__ float g_q  [BH * NSEQ * DHEAD];
__device__ float g_k  [BH * NSEQ * DHEAD];
__device__ float g_v  [BH * NSEQ * DHEAD];
__device__ float g_vsuf[BH * (NT64 + 1) * DHEAD];

// ---------------- mma.sync helpers (baseline PTX, works on compute_103) ----
__device__ __forceinline__ void mma_tf32(float* d, uint32_t a0, uint32_t a1,
                                         uint32_t a2, uint32_t a3,
                                         uint32_t b0, uint32_t b1) {
    asm volatile(
        "mma.sync.aligned.m16n8k8.row.col.f32.tf32.tf32.f32 "
        "{%0,%1,%2,%3}, {%4,%5,%6,%7}, {%8,%9}, {%0,%1,%2,%3};"
        : "+f"(d[0]), "+f"(d[1]), "+f"(d[2]), "+f"(d[3])
        : "r"(a0), "r"(a1), "r"(a2), "r"(a3), "r"(b0), "r"(b1));
}
__device__ __forceinline__ uint32_t f2tf(float x) {
    uint32_t r; asm("cvt.rna.tf32.f32 %0, %1;" : "=r"(r) : "f"(x)); return r;
}
// split x into tf32 hi + residual lo (lo passed raw; HW truncates to tf32)
__device__ __forceinline__ void split_tf(float x, uint32_t& hi, uint32_t& lo) {
    hi = f2tf(x);
    lo = __float_as_uint(x - __uint_as_float(hi));
}

// ---------------- 1) LayerNorm ----------------
__global__ __launch_bounds__(128)
void ln_kernel(const float* __restrict__ x,
               const float* __restrict__ gamma,
               const float* __restrict__ beta) {
    int row = blockIdx.x;
    int tid = threadIdx.x;
    const float4* xr = (const float4*)(x + (size_t)row * DIM);
    float4 v = xr[tid];
    float s  = v.x + v.y + v.z + v.w;
    float s2 = v.x*v.x + v.y*v.y + v.z*v.z + v.w*v.w;
    #pragma unroll
    for (int o = 16; o > 0; o >>= 1) {
        s  += __shfl_xor_sync(0xffffffffu, s,  o);
        s2 += __shfl_xor_sync(0xffffffffu, s2, o);
    }
    __shared__ float ss[4], ss2[4];
    int w = tid >> 5;
    if ((tid & 31) == 0) { ss[w] = s; ss2[w] = s2; }
    __syncthreads();
    s  = ss[0] + ss[1] + ss[2] + ss[3];
    s2 = ss2[0] + ss2[1] + ss2[2] + ss2[3];
    float mean = s * (1.0f / DIM);
    float var  = s2 * (1.0f / DIM) - mean * mean;
    float inv  = rsqrtf(var + 1e-5f);
    float4 g  = ((const float4*)gamma)[tid];
    float4 bt = ((const float4*)beta)[tid];
    float4 o;
    o.x = (v.x - mean) * inv * g.x + bt.x;
    o.y = (v.y - mean) * inv * g.y + bt.y;
    o.z = (v.z - mean) * inv * g.z + bt.z;
    o.w = (v.w - mean) * inv * g.w + bt.w;
    ((float4*)(g_hn + (size_t)row * DIM))[tid] = o;
}

// ---------------- 2) QKV GEMM via tf32 mma.sync, full hi/lo split ----------
// C[m,n] = sum_k hn[m,k] * W[n,k].  CTA tile 128m x 64n, k-chunks of 64.
// 8 warps; warp w owns rows 16w..16w+15, all 64 n-cols (8 n-tiles of 8).
#define GASTR 68
#define GEMM_SMEM ((128*GASTR + 64*GASTR) * 4)
__global__ __launch_bounds__(256, 2)
void qkv_gemm(const float* __restrict__ W) {
    extern __shared__ float sg[];
    float* As = sg;                 // [128][GASTR]
    float* Bs = sg + 128 * GASTR;   // [64][GASTR]
    const int nb = blockIdx.x * 64;
    const int mb = blockIdx.y * 128;
    const int tid = threadIdx.x;
    const int w = tid >> 5, lane = tid & 31;
    const int g = lane >> 2, q = lane & 3;
    const int r0 = w * 16;

    float C[8][4];
    #pragma unroll
    for (int n = 0; n < 8; n++)
        #pragma unroll
        for (int j = 0; j < 4; j++) C[n][j] = 0.f;

    for (int ch = 0; ch < 8; ch++) {
        const int k0 = ch * 64;
        __syncthreads();
        #pragma unroll
        for (int i = 0; i < 8; i++) {          // 128*16/256 = 8
            int idx = tid + i * 256;
            int row = idx >> 4, c4 = (idx & 15) << 2;
            *(float4*)&As[row * GASTR + c4] =
                *(const float4*)&g_hn[(size_t)(mb + row) * DIM + k0 + c4];
        }
        #pragma unroll
        for (int i = 0; i < 4; i++) {          // 64*16/256 = 4
            int idx = tid + i * 256;
            int row = idx >> 4, c4 = (idx & 15) << 2;
            *(float4*)&Bs[row * GASTR + c4] =
                *(const float4*)&W[(size_t)(nb + row) * DIM + k0 + c4];
        }
        __syncthreads();
        #pragma unroll
        for (int ks = 0; ks < 8; ks++) {
            uint32_t ah[4], al[4];
            split_tf(As[(r0 + g)     * GASTR + 8*ks + q],     ah[0], al[0]);
            split_tf(As[(r0 + g + 8) * GASTR + 8*ks + q],     ah[1], al[1]);
            split_tf(As[(r0 + g)     * GASTR + 8*ks + q + 4], ah[2], al[2]);
            split_tf(As[(r0 + g + 8) * GASTR + 8*ks + q + 4], ah[3], al[3]);
            #pragma unroll
            for (int n = 0; n < 8; n++) {
                uint32_t bh0, bl0, bh1, bl1;
                split_tf(Bs[(8*n + g) * GASTR + 8*ks + q],     bh0, bl0);
                split_tf(Bs[(8*n + g) * GASTR + 8*ks + q + 4], bh1, bl1);
                mma_tf32(C[n], ah[0], ah[1], ah[2], ah[3], bh0, bh1);
                mma_tf32(C[n], ah[0], ah[1], ah[2], ah[3], bl0, bl1);
                mma_tf32(C[n], al[0], al[1], al[2], al[3], bh0, bh1);
            }
        }
    }
    // epilogue: scatter into [B,H,N,D] q/k/v
    const int chunk = nb / 512;            // 0=q 1=k 2=v
    const int head  = (nb % 512) >> 6;
    float* dst = (chunk == 0) ? g_q : (chunk == 1) ? g_k : g_v;
    #pragma unroll
    for (int n = 0; n < 8; n++) {
        int col = 8 * n + 2 * q;
        #pragma unroll
        for (int rr = 0; rr < 2; rr++) {
            int m  = mb + r0 + g + rr * 8;
            int bi = m >> 11, nr = m & 2047;
            size_t ob = (((size_t)(bi * HEADS + head)) * NSEQ + nr) * DHEAD + col;
            *(float2*)&dst[ob] = make_float2(C[n][rr*2], C[n][rr*2 + 1]);
        }
    }
}

// ---------------- 3) V suffix column sums (parallel per-tile + scan) ------
__global__ __launch_bounds__(256)
void vsuf_kernel() {
    __shared__ float ts[NT64][DHEAD];      // per-64-row-tile column sums
    int bh  = blockIdx.x;
    int d   = threadIdx.x & 63;
    int grp = threadIdx.x >> 6;            // 0..3
    const float* V = g_v + (size_t)bh * NSEQ * DHEAD;
    for (int t = grp; t < NT64; t += 4) {
        float s = 0.f;
        #pragma unroll 8
        for (int r = 0; r < 64; r++)
            s += V[(size_t)(t * 64 + r) * DHEAD + d];
        ts[t][d] = s;
    }
    __syncthreads();
    if (threadIdx.x < 64) {
        float acc = 0.f;
        g_vsuf[((size_t)bh * (NT64 + 1) + NT64) * DHEAD + d] = 0.f;
        #pragma unroll
        for (int t = NT64 - 1; t >= 0; t--) {
            acc += ts[t][d];
            g_vsuf[((size_t)bh * (NT64 + 1) + t) * DHEAD + d] = acc;
        }
    }
}

// ---------------- 4) attention via tf32 mma.sync -----------------------
// CTA: 128 q-rows of one (b,h); key tiles of 64. 8 warps; warp w owns rows
// 16w..16w+15. QK^T split-tf32 (3 mma), P tf32-rounded (l summed from rounded
// P), PV single tf32. O + l live in registers across key tiles (no rescale:
// logits bounded). Masked tail handled as rank-1 update with V suffix sums.
#define QSTR 68
#define KSTR 68
#define VSTR 72
#define ATTN_SMEM ((128*QSTR + 64*KSTR + 64*VSTR) * 4)

__global__ __launch_bounds__(256, 2)
void attn_kernel(float* __restrict__ out) {
    extern __shared__ float sa[];
    float* Qs = sa;                       // [128][QSTR]
    float* Ks = sa + 128 * QSTR;          // [64][KSTR]
    float* Vs = Ks + 64 * KSTR;           // [64][VSTR]

    const int tid = threadIdx.x;
    const int w = tid >> 5, lane = tid & 31;
    const int g = lane >> 2, q = lane & 3;
    const int r0 = w * 16;
    const int qt = (NQT - 1) - blockIdx.x;     // big tiles first
    const int bh = blockIdx.y, b = bh >> 3, h = bh & 7;

    const float* Q = g_q + (size_t)bh * NSEQ * DHEAD;
    const float* K = g_k + (size_t)bh * NSEQ * DHEAD;
    const float* V = g_v + (size_t)bh * NSEQ * DHEAD;

    // load Q tile once
    #pragma unroll
    for (int i = 0; i < 8; i++) {
        int idx = tid + i * 256;
        int row = idx >> 4, c4 = (idx & 15) << 2;
        *(float4*)&Qs[row * QSTR + c4] =
            *(const float4*)&Q[(size_t)(qt * 128 + row) * DHEAD + c4];
    }

    float O[8][4];
    #pragma unroll
    for (int n = 0; n < 8; n++)
        #pragma unroll
        for (int j = 0; j < 4; j++) O[n][j] = 0.f;
    float ls0 = 0.f, ls1 = 0.f;

    const int qrow0 = qt * 128 + r0 + g;
    const int qrow1 = qrow0 + 8;
    const int nkt = 2 * qt + 2;

    for (int kt = 0; kt < nkt; kt++) {
        __syncthreads();
        #pragma unroll
        for (int i = 0; i < 4; i++) {          // 64*16/256 = 4
            int idx = tid + i * 256;
            int row = idx >> 4, c4 = (idx & 15) << 2;
            const float4 kv = *(const float4*)&K[(size_t)(kt*64 + row) * DHEAD + c4];
            const float4 vv = *(const float4*)&V[(size_t)(kt*64 + row) * DHEAD + c4];
            *(float4*)&Ks[row * KSTR + c4] = kv;
            *(float4*)&Vs[row * VSTR + c4] = vv;
        }
        __syncthreads();

        // ---- S = Q K^T (16 x 64 per warp), split-tf32 ----
        float S[8][4];
        #pragma unroll
        for (int n = 0; n < 8; n++)
            #pragma unroll
            for (int j = 0; j < 4; j++) S[n][j] = 0.f;
        #pragma unroll
        for (int ks = 0; ks < 8; ks++) {
            uint32_t ah[4], al[4];
            split_tf(Qs[(r0 + g)     * QSTR + 8*ks + q],     ah[0], al[0]);
            split_tf(Qs[(r0 + g + 8) * QSTR + 8*ks + q],     ah[1], al[1]);
            split_tf(Qs[(r0 + g)     * QSTR + 8*ks + q + 4], ah[2], al[2]);
            split_tf(Qs[(r0 + g + 8) * QSTR + 8*ks + q + 4], ah[3], al[3]);
            #pragma unroll
            for (int n = 0; n < 8; n++) {
                uint32_t bh0, bl0, bh1, bl1;
                split_tf(Ks[(8*n + g) * KSTR + 8*ks + q],     bh0, bl0);
                split_tf(Ks[(8*n + g) * KSTR + 8*ks + q + 4], bh1, bl1);
                mma_tf32(S[n], ah[0], ah[1], ah[2], ah[3], bh0, bh1);
                mma_tf32(S[n], ah[0], ah[1], ah[2], ah[3], bl0, bl1);
                mma_tf32(S[n], al[0], al[1], al[2], al[3], bh0, bh1);
            }
        }

        // ---- mask + exp (tf32-rounded) + lsum; transpose P; PV ----
        #pragma unroll
        for (int n = 0; n < 8; n++) {
            int kc = kt * 64 + 8 * n + 2 * q;
            float s0 = (kc     > qrow0) ? MASK_FILL : S[n][0];
            float s1 = (kc + 1 > qrow0) ? MASK_FILL : S[n][1];
            float s2 = (kc     > qrow1) ? MASK_FILL : S[n][2];
            float s3 = (kc + 1 > qrow1) ? MASK_FILL : S[n][3];
            float p0 = __uint_as_float(f2tf(__expf(s0)));
            float p1 = __uint_as_float(f2tf(__expf(s1)));
            float p2 = __uint_as_float(f2tf(__expf(s2)));
            float p3 = __uint_as_float(f2tf(__expf(s3)));
            ls0 += p0 + p1;
            ls1 += p2 + p3;
            // transpose C-frag (cols 2q,2q+1) -> A-frag (cols q, q+4)
            int src0 = (lane & ~3) | (q >> 1);
            int src1 = src0 + 2;
            float u0, u1;
            u0 = __shfl_sync(~0u, p0, src0); u1 = __shfl_sync(~0u, p1, src0);
            float a0f = (q & 1) ? u1 : u0;                  // P[g][8n+q]
            u0 = __shfl_sync(~0u, p0, src1); u1 = __shfl_sync(~0u, p1, src1);
            float a2f = (q & 1) ? u1 : u0;                  // P[g][8n+q+4]
            u0 = __shfl_sync(~0u, p2, src0); u1 = __shfl_sync(~0u, p3, src0);
            float a1f = (q & 1) ? u1 : u0;                  // P[g+8][8n+q]
            u0 = __shfl_sync(~0u, p2, src1); u1 = __shfl_sync(~0u, p3, src1);
            float a3f = (q & 1) ? u1 : u0;                  // P[g+8][8n+q+4]
            uint32_t pa0 = __float_as_uint(a0f);
            uint32_t pa1 = __float_as_uint(a1f);
            uint32_t pa2 = __float_as_uint(a2f);
            uint32_t pa3 = __float_as_uint(a3f);
            // O += P(:, 8n..8n+7) * V(8n..8n+7, :)
            #pragma unroll
            for (int n2 = 0; n2 < 8; n2++) {
                uint32_t vb0 = f2tf(Vs[(8*n + q)     * VSTR + 8*n2 + g]);
                uint32_t vb1 = f2tf(Vs[(8*n + q + 4) * VSTR + 8*n2 + g]);
                mma_tf32(O[n2], pa0, pa1, pa2, pa3, vb0, vb1);
            }
        }
    }

    // ---- reduce l across quad, fold masked tail, normalize, write ----
    ls0 += __shfl_xor_sync(~0u, ls0, 1); ls0 += __shfl_xor_sync(~0u, ls0, 2);
    ls1 += __shfl_xor_sync(~0u, ls1, 1); ls1 += __shfl_xor_sync(~0u, ls1, 2);

    const float e = __expf(MASK_FILL);      // == 1.0f in fp32
    const float cntf = (float)(NSEQ - (qt + 1) * 128);
    const float inv0 = 1.0f / (ls0 + e * cntf);
    const float inv1 = 1.0f / (ls1 + e * cntf);
    const float* vs = &g_vsuf[((size_t)bh * (NT64 + 1) + (qt + 1) * 2) * DHEAD];

    #pragma unroll
    for (int n2 = 0; n2 < 8; n2++) {
        int col = 8 * n2 + 2 * q;
        float2 vv = *(const float2*)&vs[col];
        float o00 = (O[n2][0] + e * vv.x) * inv0;
        float o01 = (O[n2][1] + e * vv.y) * inv0;
        float o10 = (O[n2][2] + e * vv.x) * inv1;
        float o11 = (O[n2][3] + e * vv.y) * inv1;
        size_t ob0 = ((size_t)b * NSEQ + qrow0) * DIM + h * DHEAD + col;
        size_t ob1 = ((size_t)b * NSEQ + qrow1) * DIM + h * DHEAD + col;
        *(float2*)&out[ob0] = make_float2(o00, o01);
        *(float2*)&out[ob1] = make_float2(o10, o11);
    }
}

// ---------------- launch ----------------
extern "C" void kernel_launch(void* const* d_in, const int* in_sizes, int n_in,
                              void* d_out, int out_size) {
    const float* x     = (const float*)d_in[0];
    const float* gamma = (const float*)d_in[1];
    const float* beta  = (const float*)d_in[2];
    const float* w_qkv = (const float*)d_in[3];
    float* out = (float*)d_out;

    cudaFuncSetAttribute(qkv_gemm, cudaFuncAttributeMaxDynamicSharedMemorySize, GEMM_SMEM);
    cudaFuncSetAttribute(attn_kernel, cudaFuncAttributeMaxDynamicSharedMemorySize, ATTN_SMEM);

    ln_kernel<<<ROWS, 128>>>(x, gamma, beta);
    qkv_gemm<<<dim3(1536 / 64, ROWS / 128), 256, GEMM_SMEM>>>(w_qkv);
    vsuf_kernel<<<BH, 256>>>();
    attn_kernel<<<dim3(NQT, BH), 256, ATTN_SMEM>>>(out);
}

// round 7
// speedup vs baseline: 3.2147x; 1.9193x over previous
#include <cuda_runtime.h>
#include <cuda_fp16.h>
#include <math.h>
#include <stdint.h>

#define BATCH 4
#define NSEQ 2048
#define DIM 512
#define HEADS 8
#define DHEAD 64
#define BH (BATCH*HEADS)      /* 32  */
#define ROWS (BATCH*NSEQ)     /* 8192 */
#define NT64 32               /* 64-row tiles (vsuf granularity) */
#define NQT 16                /* 128-row q tiles */
#define MASK_FILL 1e-8f

// ---------------- scratch ----------------
__device__ float g_hn [ROWS * DIM];
__device__ float g_q  [BH * NSEQ * DHEAD];
__device__ float g_k  [BH * NSEQ * DHEAD];
__device__ float g_v  [BH * NSEQ * DHEAD];
__device__ float g_vsuf[BH * (NT64 + 1) * DHEAD];

// ---------------- helpers ----------------
__device__ __forceinline__ void mma16(float* d, uint32_t a0, uint32_t a1,
                                      uint32_t a2, uint32_t a3,
                                      uint32_t b0, uint32_t b1) {
    asm volatile(
        "mma.sync.aligned.m16n8k16.row.col.f32.f16.f16.f32 "
        "{%0,%1,%2,%3}, {%4,%5,%6,%7}, {%8,%9}, {%0,%1,%2,%3};"
        : "+f"(d[0]), "+f"(d[1]), "+f"(d[2]), "+f"(d[3])
        : "r"(a0), "r"(a1), "r"(a2), "r"(a3), "r"(b0), "r"(b1));
}
__device__ __forceinline__ uint32_t h2u(__half2 h) {
    return *reinterpret_cast<uint32_t*>(&h);
}
__device__ __forceinline__ uint32_t pack2(float a, float b) {
    __half2 h = __floats2half2_rn(a, b);
    return h2u(h);
}
// split (x,y) into fp16 hi pair + fp16 residual pair
__device__ __forceinline__ void split2(float x, float y, uint32_t& hi, uint32_t& lo) {
    __half2 h = __floats2half2_rn(x, y);
    float2 back = __half22float2(h);
    hi = h2u(h);
    lo = pack2(x - back.x, y - back.y);
}

// ---------------- 1) LayerNorm ----------------
__global__ __launch_bounds__(128)
void ln_kernel(const float* __restrict__ x,
               const float* __restrict__ gamma,
               const float* __restrict__ beta) {
    int row = blockIdx.x;
    int tid = threadIdx.x;
    const float4* xr = (const float4*)(x + (size_t)row * DIM);
    float4 v = xr[tid];
    float s  = v.x + v.y + v.z + v.w;
    float s2 = v.x*v.x + v.y*v.y + v.z*v.z + v.w*v.w;
    #pragma unroll
    for (int o = 16; o > 0; o >>= 1) {
        s  += __shfl_xor_sync(0xffffffffu, s,  o);
        s2 += __shfl_xor_sync(0xffffffffu, s2, o);
    }
    __shared__ float ss[4], ss2[4];
    int w = tid >> 5;
    if ((tid & 31) == 0) { ss[w] = s; ss2[w] = s2; }
    __syncthreads();
    s  = ss[0] + ss[1] + ss[2] + ss[3];
    s2 = ss2[0] + ss2[1] + ss2[2] + ss2[3];
    float mean = s * (1.0f / DIM);
    float var  = s2 * (1.0f / DIM) - mean * mean;
    float inv  = rsqrtf(var + 1e-5f);
    float4 g  = ((const float4*)gamma)[tid];
    float4 bt = ((const float4*)beta)[tid];
    float4 o;
    o.x = (v.x - mean) * inv * g.x + bt.x;
    o.y = (v.y - mean) * inv * g.y + bt.y;
    o.z = (v.z - mean) * inv * g.z + bt.z;
    o.w = (v.w - mean) * inv * g.w + bt.w;
    ((float4*)(g_hn + (size_t)row * DIM))[tid] = o;
}

// ---------------- 2) QKV GEMM: fp16 split mma (3-term) ----------------
// C[m,n] = sum_k hn[m,k] W[n,k].  CTA 128m x 64n, k-chunks of 64.
// smem: Ahi/Alo [128][72]h, Bhi/Blo [64][72]h  (72-half stride = 36 words,
// bank-perfect for frag loads: (4g+q) mod 32 all distinct).
#define GAHI 0
#define GALO 18432
#define GBHI 36864
#define GBLO 46080
#define GEMM_SMEM 55296
__global__ __launch_bounds__(256, 2)
void qkv_gemm(const float* __restrict__ W) {
    extern __shared__ char smc[];
    uint32_t* AHIw = (uint32_t*)(smc + GAHI);
    uint32_t* ALOw = (uint32_t*)(smc + GALO);
    uint32_t* BHIw = (uint32_t*)(smc + GBHI);
    uint32_t* BLOw = (uint32_t*)(smc + GBLO);
    const int nb = blockIdx.x * 64;
    const int mb = blockIdx.y * 128;
    const int tid = threadIdx.x;
    const int w = tid >> 5, lane = tid & 31;
    const int g = lane >> 2, q = lane & 3;
    const int r0 = w * 16;

    float C[8][4];
    #pragma unroll
    for (int n = 0; n < 8; n++)
        #pragma unroll
        for (int j = 0; j < 4; j++) C[n][j] = 0.f;

    for (int ch = 0; ch < 8; ch++) {
        const int k0 = ch * 64;
        __syncthreads();
        #pragma unroll
        for (int i = 0; i < 8; i++) {              // A: 128 rows x 16 f4
            int idx = tid + i * 256;
            int row = idx >> 4, c4 = (idx & 15) << 2;
            float4 v = *(const float4*)&g_hn[(size_t)(mb + row) * DIM + k0 + c4];
            uint32_t h0, l0, h1, l1;
            split2(v.x, v.y, h0, l0); split2(v.z, v.w, h1, l1);
            *(uint2*)(AHIw + row * 36 + (c4 >> 1)) = make_uint2(h0, h1);
            *(uint2*)(ALOw + row * 36 + (c4 >> 1)) = make_uint2(l0, l1);
        }
        #pragma unroll
        for (int i = 0; i < 4; i++) {              // B: 64 rows x 16 f4
            int idx = tid + i * 256;
            int row = idx >> 4, c4 = (idx & 15) << 2;
            float4 v = *(const float4*)&W[(size_t)(nb + row) * DIM + k0 + c4];
            uint32_t h0, l0, h1, l1;
            split2(v.x, v.y, h0, l0); split2(v.z, v.w, h1, l1);
            *(uint2*)(BHIw + row * 36 + (c4 >> 1)) = make_uint2(h0, h1);
            *(uint2*)(BLOw + row * 36 + (c4 >> 1)) = make_uint2(l0, l1);
        }
        __syncthreads();
        #pragma unroll
        for (int ks = 0; ks < 4; ks++) {
            int a0w = (r0 + g) * 36 + 8 * ks + q;
            int a1w = (r0 + g + 8) * 36 + 8 * ks + q;
            uint32_t ah0 = AHIw[a0w],     ah1 = AHIw[a1w];
            uint32_t ah2 = AHIw[a0w + 4], ah3 = AHIw[a1w + 4];
            uint32_t al0 = ALOw[a0w],     al1 = ALOw[a1w];
            uint32_t al2 = ALOw[a0w + 4], al3 = ALOw[a1w + 4];
            #pragma unroll
            for (int n = 0; n < 8; n++) {
                int bw = (8 * n + g) * 36 + 8 * ks + q;
                uint32_t bh0 = BHIw[bw], bh1 = BHIw[bw + 4];
                uint32_t bl0 = BLOw[bw], bl1 = BLOw[bw + 4];
                mma16(C[n], ah0, ah1, ah2, ah3, bh0, bh1);
                mma16(C[n], ah0, ah1, ah2, ah3, bl0, bl1);
                mma16(C[n], al0, al1, al2, al3, bh0, bh1);
            }
        }
    }
    const int chunk = nb / 512;            // 0=q 1=k 2=v
    const int head  = (nb % 512) >> 6;
    float* dst = (chunk == 0) ? g_q : (chunk == 1) ? g_k : g_v;
    #pragma unroll
    for (int n = 0; n < 8; n++) {
        int col = 8 * n + 2 * q;
        #pragma unroll
        for (int rr = 0; rr < 2; rr++) {
            int m  = mb + r0 + g + rr * 8;
            int bi = m >> 11, nr = m & 2047;
            size_t ob = (((size_t)(bi * HEADS + head)) * NSEQ + nr) * DHEAD + col;
            *(float2*)&dst[ob] = make_float2(C[n][rr*2], C[n][rr*2 + 1]);
        }
    }
}

// ---------------- 3) V suffix column sums (parallel per-tile + scan) ------
__global__ __launch_bounds__(256)
void vsuf_kernel() {
    __shared__ float ts[NT64][DHEAD];
    int bh  = blockIdx.x;
    int d   = threadIdx.x & 63;
    int grp = threadIdx.x >> 6;
    const float* V = g_v + (size_t)bh * NSEQ * DHEAD;
    for (int t = grp; t < NT64; t += 4) {
        float s = 0.f;
        #pragma unroll 8
        for (int r = 0; r < 64; r++)
            s += V[(size_t)(t * 64 + r) * DHEAD + d];
        ts[t][d] = s;
    }
    __syncthreads();
    if (threadIdx.x < 64) {
        float acc = 0.f;
        g_vsuf[((size_t)bh * (NT64 + 1) + NT64) * DHEAD + d] = 0.f;
        #pragma unroll
        for (int t = NT64 - 1; t >= 0; t--) {
            acc += ts[t][d];
            g_vsuf[((size_t)bh * (NT64 + 1) + t) * DHEAD + d] = acc;
        }
    }
}

// ---------------- 4) attention: fp16 mma, zero-shuffle P reuse ------------
// CTA: 128 q-rows of one (b,h), key tiles of 64, 8 warps (16 rows each).
// QK^T: 3-term fp16 split (Qhi*Khi + Qhi*Klo + Qlo*Khi); online per-tile max
// (fp16 range); P = fp16(exp(s-m)) reused directly as PV A-frag (C-frag
// column pairing == A-frag half2 pairing); l summed from the rounded P.
// Masked tail (uniform logits 1e-8) folded as exact rank-1 via V suffix sums.
#define AQHI 0
#define AQLO 18432
#define AKHI 36864
#define AKLO 46080
#define AVP  55296
#define ATTN_SMEM 64512

__global__ __launch_bounds__(256, 2)
void attn_kernel(float* __restrict__ out) {
    extern __shared__ char smc[];
    uint32_t* QHIw = (uint32_t*)(smc + AQHI);
    uint32_t* QLOw = (uint32_t*)(smc + AQLO);
    uint32_t* KHIw = (uint32_t*)(smc + AKHI);
    uint32_t* KLOw = (uint32_t*)(smc + AKLO);
    uint32_t* VPw  = (uint32_t*)(smc + AVP);   // [32][72] half2 (key pairs)

    const int tid = threadIdx.x;
    const int w = tid >> 5, lane = tid & 31;
    const int g = lane >> 2, q = lane & 3;
    const int r0 = w * 16;
    const int qt = (NQT - 1) - blockIdx.x;     // big tiles first
    const int bh = blockIdx.y, b = bh >> 3, h = bh & 7;

    const float* Q = g_q + (size_t)bh * NSEQ * DHEAD;
    const float* K = g_k + (size_t)bh * NSEQ * DHEAD;
    const float* V = g_v + (size_t)bh * NSEQ * DHEAD;

    // Q tile -> split fp16 smem (once)
    #pragma unroll
    for (int i = 0; i < 8; i++) {
        int idx = tid + i * 256;
        int row = idx >> 4, c4 = (idx & 15) << 2;
        float4 v = *(const float4*)&Q[(size_t)(qt * 128 + row) * DHEAD + c4];
        uint32_t h0, l0, h1, l1;
        split2(v.x, v.y, h0, l0); split2(v.z, v.w, h1, l1);
        *(uint2*)(QHIw + row * 36 + (c4 >> 1)) = make_uint2(h0, h1);
        *(uint2*)(QLOw + row * 36 + (c4 >> 1)) = make_uint2(l0, l1);
    }

    float O[8][4];
    #pragma unroll
    for (int n = 0; n < 8; n++)
        #pragma unroll
        for (int j = 0; j < 4; j++) O[n][j] = 0.f;
    float ls0 = 0.f, ls1 = 0.f;
    float m0 = -1e30f, m1 = -1e30f;

    const int qrow0 = qt * 128 + r0 + g;
    const int qrow1 = qrow0 + 8;
    const int nkt = 2 * qt + 2;

    for (int kt = 0; kt < nkt; kt++) {
        __syncthreads();
        // K tile -> split fp16
        #pragma unroll
        for (int i = 0; i < 4; i++) {
            int idx = tid + i * 256;
            int row = idx >> 4, c4 = (idx & 15) << 2;
            float4 v = *(const float4*)&K[(size_t)(kt * 64 + row) * DHEAD + c4];
            uint32_t h0, l0, h1, l1;
            split2(v.x, v.y, h0, l0); split2(v.z, v.w, h1, l1);
            *(uint2*)(KHIw + row * 36 + (c4 >> 1)) = make_uint2(h0, h1);
            *(uint2*)(KLOw + row * 36 + (c4 >> 1)) = make_uint2(l0, l1);
        }
        // V tile -> key-pair packed half2: Vp[r2][d] = (V[2r2][d], V[2r2+1][d])
        #pragma unroll
        for (int i = 0; i < 2; i++) {
            int idx = tid + i * 256;
            int r2 = idx >> 4, c4 = (idx & 15) << 2;
            const float* vp = &V[(size_t)(kt * 64 + 2 * r2) * DHEAD + c4];
            float4 va = *(const float4*)vp;
            float4 vb = *(const float4*)(vp + DHEAD);
            *(uint4*)(VPw + r2 * 72 + c4) =
                make_uint4(pack2(va.x, vb.x), pack2(va.y, vb.y),
                           pack2(va.z, vb.z), pack2(va.w, vb.w));
        }
        __syncthreads();

        // ---- S = Q K^T (16x64 per warp), 3-term fp16 split ----
        float S[8][4];
        #pragma unroll
        for (int n = 0; n < 8; n++)
            #pragma unroll
            for (int j = 0; j < 4; j++) S[n][j] = 0.f;
        #pragma unroll
        for (int ks = 0; ks < 4; ks++) {
            int a0w = (r0 + g) * 36 + 8 * ks + q;
            int a1w = (r0 + g + 8) * 36 + 8 * ks + q;
            uint32_t qh0 = QHIw[a0w],     qh1 = QHIw[a1w];
            uint32_t qh2 = QHIw[a0w + 4], qh3 = QHIw[a1w + 4];
            uint32_t ql0 = QLOw[a0w],     ql1 = QLOw[a1w];
            uint32_t ql2 = QLOw[a0w + 4], ql3 = QLOw[a1w + 4];
            #pragma unroll
            for (int n = 0; n < 8; n++) {
                int bw = (8 * n + g) * 36 + 8 * ks + q;
                uint32_t bh0 = KHIw[bw], bh1 = KHIw[bw + 4];
                uint32_t bl0 = KLOw[bw], bl1 = KLOw[bw + 4];
                mma16(S[n], qh0, qh1, qh2, qh3, bh0, bh1);
                mma16(S[n], qh0, qh1, qh2, qh3, bl0, bl1);
                mma16(S[n], ql0, ql1, ql2, ql3, bh0, bh1);
            }
        }

        // ---- mask (diagonal tiles only) ----
        if (kt >= 2 * qt) {
            #pragma unroll
            for (int n = 0; n < 8; n++) {
                int kc = kt * 64 + 8 * n + 2 * q;
                if (kc     > qrow0) S[n][0] = MASK_FILL;
                if (kc + 1 > qrow0) S[n][1] = MASK_FILL;
                if (kc     > qrow1) S[n][2] = MASK_FILL;
                if (kc + 1 > qrow1) S[n][3] = MASK_FILL;
            }
        }

        // ---- online max (coarse, per tile) ----
        float rm0 = -1e30f, rm1 = -1e30f;
        #pragma unroll
        for (int n = 0; n < 8; n++) {
            rm0 = fmaxf(rm0, fmaxf(S[n][0], S[n][1]));
            rm1 = fmaxf(rm1, fmaxf(S[n][2], S[n][3]));
        }
        rm0 = fmaxf(rm0, __shfl_xor_sync(~0u, rm0, 1));
        rm0 = fmaxf(rm0, __shfl_xor_sync(~0u, rm0, 2));
        rm1 = fmaxf(rm1, __shfl_xor_sync(~0u, rm1, 1));
        rm1 = fmaxf(rm1, __shfl_xor_sync(~0u, rm1, 2));
        float mn0 = fmaxf(m0, rm0), mn1 = fmaxf(m1, rm1);
        float sc0 = __expf(m0 - mn0), sc1 = __expf(m1 - mn1);
        m0 = mn0; m1 = mn1;
        ls0 *= sc0; ls1 *= sc1;
        #pragma unroll
        for (int n = 0; n < 8; n++) {
            O[n][0] *= sc0; O[n][1] *= sc0;
            O[n][2] *= sc1; O[n][3] *= sc1;
        }

        // ---- exp -> fp16 P (A-frags directly); l from rounded P ----
        uint32_t u01[8], u23[8];
        #pragma unroll
        for (int n = 0; n < 8; n++) {
            float p0 = __expf(S[n][0] - mn0), p1 = __expf(S[n][1] - mn0);
            float p2 = __expf(S[n][2] - mn1), p3 = __expf(S[n][3] - mn1);
            __half2 hp01 = __floats2half2_rn(p0, p1);
            __half2 hp23 = __floats2half2_rn(p2, p3);
            u01[n] = h2u(hp01); u23[n] = h2u(hp23);
            float2 f01 = __half22float2(hp01);
            float2 f23 = __half22float2(hp23);
            ls0 += f01.x + f01.y;
            ls1 += f23.x + f23.y;
        }

        // ---- O += P V ----
        #pragma unroll
        for (int kp = 0; kp < 4; kp++) {
            uint32_t a0 = u01[2*kp],     a1 = u23[2*kp];
            uint32_t a2 = u01[2*kp + 1], a3 = u23[2*kp + 1];
            #pragma unroll
            for (int n2 = 0; n2 < 8; n2++) {
                uint32_t b0 = VPw[(8*kp + q)     * 72 + 8*n2 + g];
                uint32_t b1 = VPw[(8*kp + q + 4) * 72 + 8*n2 + g];
                mma16(O[n2], a0, a1, a2, a3, b0, b1);
            }
        }
    }

    // ---- reduce l over quad, fold masked tail (rank-1), normalize, write --
    ls0 += __shfl_xor_sync(~0u, ls0, 1); ls0 += __shfl_xor_sync(~0u, ls0, 2);
    ls1 += __shfl_xor_sync(~0u, ls1, 1); ls1 += __shfl_xor_sync(~0u, ls1, 2);

    const float cntf = (float)(NSEQ - (qt + 1) * 128);
    const float e0 = __expf(MASK_FILL - m0);
    const float e1 = __expf(MASK_FILL - m1);
    const float inv0 = 1.0f / (ls0 + e0 * cntf);
    const float inv1 = 1.0f / (ls1 + e1 * cntf);
    const float* vs = &g_vsuf[((size_t)bh * (NT64 + 1) + (qt + 1) * 2) * DHEAD];

    #pragma unroll
    for (int n2 = 0; n2 < 8; n2++) {
        int col = 8 * n2 + 2 * q;
        float2 vv = *(const float2*)&vs[col];
        float o00 = (O[n2][0] + e0 * vv.x) * inv0;
        float o01 = (O[n2][1] + e0 * vv.y) * inv0;
        float o10 = (O[n2][2] + e1 * vv.x) * inv1;
        float o11 = (O[n2][3] + e1 * vv.y) * inv1;
        size_t ob0 = ((size_t)b * NSEQ + qrow0) * DIM + h * DHEAD + col;
        size_t ob1 = ((size_t)b * NSEQ + qrow1) * DIM + h * DHEAD + col;
        *(float2*)&out[ob0] = make_float2(o00, o01);
        *(float2*)&out[ob1] = make_float2(o10, o11);
    }
}

// ---------------- launch ----------------
extern "C" void kernel_launch(void* const* d_in, const int* in_sizes, int n_in,
                              void* d_out, int out_size) {
    const float* x     = (const float*)d_in[0];
    const float* gamma = (const float*)d_in[1];
    const float* beta  = (const float*)d_in[2];
    const float* w_qkv = (const float*)d_in[3];
    float* out = (float*)d_out;

    cudaFuncSetAttribute(qkv_gemm, cudaFuncAttributeMaxDynamicSharedMemorySize, GEMM_SMEM);
    cudaFuncSetAttribute(attn_kernel, cudaFuncAttributeMaxDynamicSharedMemorySize, ATTN_SMEM);

    ln_kernel<<<ROWS, 128>>>(x, gamma, beta);
    qkv_gemm<<<dim3(1536 / 64, ROWS / 128), 256, GEMM_SMEM>>>(w_qkv);
    vsuf_kernel<<<BH, 256>>>();
    attn_kernel<<<dim3(NQT, BH), 256, ATTN_SMEM>>>(out);
}

// round 10
// speedup vs baseline: 3.3044x; 1.0279x over previous
#include <cuda_runtime.h>
#include <cuda_fp16.h>
#include <math.h>
#include <stdint.h>

#define BATCH 4
#define NSEQ 2048
#define DIM 512
#define HEADS 8
#define DHEAD 64
#define BH (BATCH*HEADS)      /* 32  */
#define ROWS (BATCH*NSEQ)     /* 8192 */
#define NT64 32               /* 64-row k tiles */
#define NQT 16                /* 128-row q tiles */
#define MASK_FILL 1e-8f

// ---------------- scratch ----------------
__device__ float g_hn [ROWS * DIM];
__device__ float g_v  [BH * NSEQ * DHEAD];          // fp32 V (vsuf)
__device__ float g_vsuf[BH * (NT64 + 1) * DHEAD];
// MMA-ready fp16 images (exact smem layout, 36-word row stride / VP 72)
__device__ uint32_t g_qih[BH * NQT * 128 * 36];
__device__ uint32_t g_qil[BH * NQT * 128 * 36];
__device__ uint32_t g_kih[BH * NT64 * 64 * 36];
__device__ uint32_t g_kil[BH * NT64 * 64 * 36];
__device__ uint32_t g_vp [BH * NT64 * 32 * 72];

// ---------------- helpers ----------------
__device__ __forceinline__ void mma16(float* d, uint32_t a0, uint32_t a1,
                                      uint32_t a2, uint32_t a3,
                                      uint32_t b0, uint32_t b1) {
    asm volatile(
        "mma.sync.aligned.m16n8k16.row.col.f32.f16.f16.f32 "
        "{%0,%1,%2,%3}, {%4,%5,%6,%7}, {%8,%9}, {%0,%1,%2,%3};"
        : "+f"(d[0]), "+f"(d[1]), "+f"(d[2]), "+f"(d[3])
        : "r"(a0), "r"(a1), "r"(a2), "r"(a3), "r"(b0), "r"(b1));
}
__device__ __forceinline__ uint32_t h2u(__half2 h) {
    return *reinterpret_cast<uint32_t*>(&h);
}
__device__ __forceinline__ uint32_t pack2(float a, float b) {
    __half2 h = __floats2half2_rn(a, b);
    return h2u(h);
}
__device__ __forceinline__ void split2(float x, float y, uint32_t& hi, uint32_t& lo) {
    __half2 h = __floats2half2_rn(x, y);
    float2 back = __half22float2(h);
    hi = h2u(h);
    lo = pack2(x - back.x, y - back.y);
}
__device__ __forceinline__ uint32_t smem_u32(const void* p) {
    uint32_t a;
    asm("{ .reg .u64 t; cvta.to.shared.u64 t, %1; cvt.u32.u64 %0, t; }" : "=r"(a) : "l"(p));
    return a;
}
#define CPA16(dst, src) \
    asm volatile("cp.async.cg.shared.global [%0], [%1], 16;" :: "r"(dst), "l"(src) : "memory")
#define CP_COMMIT() asm volatile("cp.async.commit_group;" ::: "memory")
#define CP_WAIT0()  asm volatile("cp.async.wait_group 0;" ::: "memory")

// ---------------- 1) LayerNorm ----------------
__global__ __launch_bounds__(128)
void ln_kernel(const float* __restrict__ x,
               const float* __restrict__ gamma,
               const float* __restrict__ beta) {
    int row = blockIdx.x;
    int tid = threadIdx.x;
    const float4* xr = (const float4*)(x + (size_t)row * DIM);
    float4 v = xr[tid];
    float s  = v.x + v.y + v.z + v.w;
    float s2 = v.x*v.x + v.y*v.y + v.z*v.z + v.w*v.w;
    #pragma unroll
    for (int o = 16; o > 0; o >>= 1) {
        s  += __shfl_xor_sync(0xffffffffu, s,  o);
        s2 += __shfl_xor_sync(0xffffffffu, s2, o);
    }
    __shared__ float ss[4], ss2[4];
    int w = tid >> 5;
    if ((tid & 31) == 0) { ss[w] = s; ss2[w] = s2; }
    __syncthreads();
    s  = ss[0] + ss[1] + ss[2] + ss[3];
    s2 = ss2[0] + ss2[1] + ss2[2] + ss2[3];
    float mean = s * (1.0f / DIM);
    float var  = s2 * (1.0f / DIM) - mean * mean;
    float inv  = rsqrtf(var + 1e-5f);
    float4 g  = ((const float4*)gamma)[tid];
    float4 bt = ((const float4*)beta)[tid];
    float4 o;
    o.x = (v.x - mean) * inv * g.x + bt.x;
    o.y = (v.y - mean) * inv * g.y + bt.y;
    o.z = (v.z - mean) * inv * g.z + bt.z;
    o.w = (v.w - mean) * inv * g.w + bt.w;
    ((float4*)(g_hn + (size_t)row * DIM))[tid] = o;
}

// ---------------- 2) QKV GEMM: fp16 3-term split, cp.async staged ---------
#define GAHI 0
#define GALO 18432
#define GBHI 36864
#define GBLO 46080
#define GRAWA 55296
#define GRAWB 88064
#define GEMM_SMEM 104448
__global__ __launch_bounds__(256, 2)
void qkv_gemm(const float* __restrict__ W) {
    extern __shared__ char smc[];
    uint32_t* AHIw = (uint32_t*)(smc + GAHI);
    uint32_t* ALOw = (uint32_t*)(smc + GALO);
    uint32_t* BHIw = (uint32_t*)(smc + GBHI);
    uint32_t* BLOw = (uint32_t*)(smc + GBLO);
    const float4* rawA = (const float4*)(smc + GRAWA);   // [128][16]
    const float4* rawB = (const float4*)(smc + GRAWB);   // [64][16]
    const uint32_t sb = smem_u32(smc);
    const int nb = blockIdx.x * 64;
    const int mb = blockIdx.y * 128;
    const int tid = threadIdx.x;
    const int w = tid >> 5, lane = tid & 31;
    const int g = lane >> 2, q = lane & 3;
    const int r0 = w * 16;

    float C[8][4];
    #pragma unroll
    for (int n = 0; n < 8; n++)
        #pragma unroll
        for (int j = 0; j < 4; j++) C[n][j] = 0.f;

    // prefetch chunk 0
    #pragma unroll
    for (int i = 0; i < 12; i++) {
        int c = tid + i * 256;
        if (c < 2048) {
            CPA16(sb + GRAWA + c * 16,
                  &g_hn[(size_t)(mb + (c >> 4)) * DIM + ((c & 15) << 2)]);
        } else {
            int c2 = c - 2048;
            CPA16(sb + GRAWB + c2 * 16,
                  &W[(size_t)(nb + (c2 >> 4)) * DIM + ((c2 & 15) << 2)]);
        }
    }
    CP_COMMIT();

    for (int ch = 0; ch < 8; ch++) {
        CP_WAIT0();
        __syncthreads();
        // convert raw -> fp16 split bufs
        #pragma unroll
        for (int i = 0; i < 8; i++) {
            int idx = tid + i * 256;
            int row = idx >> 4, cf = idx & 15;
            float4 v = rawA[row * 16 + cf];
            uint32_t h0, l0, h1, l1;
            split2(v.x, v.y, h0, l0); split2(v.z, v.w, h1, l1);
            *(uint2*)(AHIw + row * 36 + 2 * cf) = make_uint2(h0, h1);
            *(uint2*)(ALOw + row * 36 + 2 * cf) = make_uint2(l0, l1);
        }
        #pragma unroll
        for (int i = 0; i < 4; i++) {
            int idx = tid + i * 256;
            int row = idx >> 4, cf = idx & 15;
            float4 v = rawB[row * 16 + cf];
            uint32_t h0, l0, h1, l1;
            split2(v.x, v.y, h0, l0); split2(v.z, v.w, h1, l1);
            *(uint2*)(BHIw + row * 36 + 2 * cf) = make_uint2(h0, h1);
            *(uint2*)(BLOw + row * 36 + 2 * cf) = make_uint2(l0, l1);
        }
        __syncthreads();
        // prefetch chunk ch+1 (overlaps with compute below)
        if (ch + 1 < 8) {
            const int k0 = (ch + 1) * 64;
            #pragma unroll
            for (int i = 0; i < 12; i++) {
                int c = tid + i * 256;
                if (c < 2048) {
                    CPA16(sb + GRAWA + c * 16,
                          &g_hn[(size_t)(mb + (c >> 4)) * DIM + k0 + ((c & 15) << 2)]);
                } else {
                    int c2 = c - 2048;
                    CPA16(sb + GRAWB + c2 * 16,
                          &W[(size_t)(nb + (c2 >> 4)) * DIM + k0 + ((c2 & 15) << 2)]);
                }
            }
            CP_COMMIT();
        }
        // compute
        #pragma unroll
        for (int ks = 0; ks < 4; ks++) {
            int a0w = (r0 + g) * 36 + 8 * ks + q;
            int a1w = (r0 + g + 8) * 36 + 8 * ks + q;
            uint32_t ah0 = AHIw[a0w],     ah1 = AHIw[a1w];
            uint32_t ah2 = AHIw[a0w + 4], ah3 = AHIw[a1w + 4];
            uint32_t al0 = ALOw[a0w],     al1 = ALOw[a1w];
            uint32_t al2 = ALOw[a0w + 4], al3 = ALOw[a1w + 4];
            #pragma unroll
            for (int n = 0; n < 8; n++) {
                int bw = (8 * n + g) * 36 + 8 * ks + q;
                uint32_t bh0 = BHIw[bw], bh1 = BHIw[bw + 4];
                uint32_t bl0 = BLOw[bw], bl1 = BLOw[bw + 4];
                mma16(C[n], ah0, ah1, ah2, ah3, bh0, bh1);
                mma16(C[n], ah0, ah1, ah2, ah3, bl0, bl1);
                mma16(C[n], al0, al1, al2, al3, bh0, bh1);
            }
        }
    }

    // ---- epilogue: emit MMA-ready images (q,k) / fp32 + VP image (v) ----
    const int chunk = nb / 512;            // 0=q 1=k 2=v
    const int head  = (nb % 512) >> 6;
    if (chunk == 0) {
        #pragma unroll
        for (int n = 0; n < 8; n++)
            #pragma unroll
            for (int rr = 0; rr < 2; rr++) {
                int m  = mb + r0 + g + rr * 8;
                int bi = m >> 11, nr = m & 2047;
                int bhh = bi * HEADS + head;
                size_t idx = ((size_t)(bhh * NQT + (nr >> 7)) * 128 + (nr & 127)) * 36 + 4 * n + q;
                uint32_t hi, lo;
                split2(C[n][rr * 2], C[n][rr * 2 + 1], hi, lo);
                g_qih[idx] = hi; g_qil[idx] = lo;
            }
    } else if (chunk == 1) {
        #pragma unroll
        for (int n = 0; n < 8; n++)
            #pragma unroll
            for (int rr = 0; rr < 2; rr++) {
                int m  = mb + r0 + g + rr * 8;
                int bi = m >> 11, nr = m & 2047;
                int bhh = bi * HEADS + head;
                size_t idx = ((size_t)(bhh * NT64 + (nr >> 6)) * 64 + (nr & 63)) * 36 + 4 * n + q;
                uint32_t hi, lo;
                split2(C[n][rr * 2], C[n][rr * 2 + 1], hi, lo);
                g_kih[idx] = hi; g_kil[idx] = lo;
            }
    } else {
        // fp32 V for vsuf
        #pragma unroll
        for (int n = 0; n < 8; n++) {
            int col = 8 * n + 2 * q;
            #pragma unroll
            for (int rr = 0; rr < 2; rr++) {
                int m  = mb + r0 + g + rr * 8;
                int bi = m >> 11, nr = m & 2047;
                size_t ob = (((size_t)(bi * HEADS + head)) * NSEQ + nr) * DHEAD + col;
                *(float2*)&g_v[ob] = make_float2(C[n][rr * 2], C[n][rr * 2 + 1]);
            }
        }
        // VP image: half2 word [r2][d] = (V[2r2][d], V[2r2+1][d]); even-g lanes
        #pragma unroll
        for (int n = 0; n < 8; n++) {
            float p0 = __shfl_xor_sync(~0u, C[n][0], 4);
            float p1 = __shfl_xor_sync(~0u, C[n][1], 4);
            float p2 = __shfl_xor_sync(~0u, C[n][2], 4);
            float p3 = __shfl_xor_sync(~0u, C[n][3], 4);
            if ((g & 1) == 0) {
                int m0 = mb + r0 + g;
                int bi = m0 >> 11, nr = m0 & 2047;
                int bhh = bi * HEADS + head;
                size_t base = (size_t)(bhh * NT64 + (nr >> 6)) * (32 * 72);
                int r2 = (nr & 63) >> 1;
                int dw = 8 * n + 2 * q;
                *(uint2*)&g_vp[base + (size_t)r2 * 72 + dw] =
                    make_uint2(pack2(C[n][0], p0), pack2(C[n][1], p1));
                *(uint2*)&g_vp[base + (size_t)(r2 + 4) * 72 + dw] =
                    make_uint2(pack2(C[n][2], p2), pack2(C[n][3], p3));
            }
        }
    }
}

// ---------------- 3) V suffix column sums ----------------
__global__ __launch_bounds__(256)
void vsuf_kernel() {
    __shared__ float ts[NT64][DHEAD];
    int bh  = blockIdx.x;
    int d   = threadIdx.x & 63;
    int grp = threadIdx.x >> 6;
    const float* V = g_v + (size_t)bh * NSEQ * DHEAD;
    for (int t = grp; t < NT64; t += 4) {
        float s = 0.f;
        #pragma unroll 8
        for (int r = 0; r < 64; r++)
            s += V[(size_t)(t * 64 + r) * DHEAD + d];
        ts[t][d] = s;
    }
    __syncthreads();
    if (threadIdx.x < 64) {
        float acc = 0.f;
        g_vsuf[((size_t)bh * (NT64 + 1) + NT64) * DHEAD + d] = 0.f;
        #pragma unroll
        for (int t = NT64 - 1; t >= 0; t--) {
            acc += ts[t][d];
            g_vsuf[((size_t)bh * (NT64 + 1) + t) * DHEAD + d] = acc;
        }
    }
}

// ---------------- 4) attention: cp.async images + fp16 mma ----------------
// Per-tile: one flat cp.async of (Khi,Klo,VP) image into double-buffered
// stage (prefetched during previous tile's compute), then pure MMA+softmax.
#define AQHI 0
#define AQLO 18432
#define ASTG 36864
#define STG_SZ 27648          /* KHI 9216 | KLO 9216 | VP 9216 */
#define ATTN_SMEM 92160

__global__ __launch_bounds__(256, 2)
void attn_kernel(float* __restrict__ out) {
    extern __shared__ char smc[];
    const uint32_t sb = smem_u32(smc);
    uint32_t* QHIw = (uint32_t*)(smc + AQHI);
    uint32_t* QLOw = (uint32_t*)(smc + AQLO);

    const int tid = threadIdx.x;
    const int w = tid >> 5, lane = tid & 31;
    const int g = lane >> 2, q = lane & 3;
    const int r0 = w * 16;
    const int qt = (NQT - 1) - blockIdx.x;     // big tiles first
    const int bh = blockIdx.y, b = bh >> 3, h = bh & 7;
    const int nkt = 2 * qt + 2;

    // Q images (hi+lo, 2*18432B) + K/V tile 0 -> stage 0, one group
    {
        const char* qh = (const char*)&g_qih[(size_t)(bh * NQT + qt) * 4608];
        const char* ql = (const char*)&g_qil[(size_t)(bh * NQT + qt) * 4608];
        #pragma unroll
        for (int i = 0; i < 9; i++) {
            int c = tid + i * 256;
            if (c < 1152) CPA16(sb + AQHI + c * 16, qh + c * 16);
            else          CPA16(sb + AQLO + (c - 1152) * 16, ql + (c - 1152) * 16);
        }
        const char* kh = (const char*)&g_kih[(size_t)(bh * NT64 + 0) * 2304];
        const char* kl = (const char*)&g_kil[(size_t)(bh * NT64 + 0) * 2304];
        const char* vp = (const char*)&g_vp [(size_t)(bh * NT64 + 0) * 2304];
        #pragma unroll
        for (int i = 0; i < 7; i++) {
            int c = tid + i * 256;
            if (c < 576)       CPA16(sb + ASTG + c * 16, kh + c * 16);
            else if (c < 1152) CPA16(sb + ASTG + 9216 + (c - 576) * 16, kl + (c - 576) * 16);
            else if (c < 1728) CPA16(sb + ASTG + 18432 + (c - 1152) * 16, vp + (c - 1152) * 16);
        }
        CP_COMMIT();
    }

    float O[8][4];
    #pragma unroll
    for (int n = 0; n < 8; n++)
        #pragma unroll
        for (int j = 0; j < 4; j++) O[n][j] = 0.f;
    float ls0 = 0.f, ls1 = 0.f;
    float m0 = -1e30f, m1 = -1e30f;

    const int qrow0 = qt * 128 + r0 + g;
    const int qrow1 = qrow0 + 8;

    for (int kt = 0; kt < nkt; kt++) {
        CP_WAIT0();
        __syncthreads();
        // prefetch tile kt+1 into the other stage (overlaps compute below)
        if (kt + 1 < nkt) {
            uint32_t dst = sb + ASTG + ((kt + 1) & 1) * STG_SZ;
            const char* kh = (const char*)&g_kih[(size_t)(bh * NT64 + kt + 1) * 2304];
            const char* kl = (const char*)&g_kil[(size_t)(bh * NT64 + kt + 1) * 2304];
            const char* vp = (const char*)&g_vp [(size_t)(bh * NT64 + kt + 1) * 2304];
            #pragma unroll
            for (int i = 0; i < 7; i++) {
                int c = tid + i * 256;
                if (c < 576)       CPA16(dst + c * 16, kh + c * 16);
                else if (c < 1152) CPA16(dst + 9216 + (c - 576) * 16, kl + (c - 576) * 16);
                else if (c < 1728) CPA16(dst + 18432 + (c - 1152) * 16, vp + (c - 1152) * 16);
            }
            CP_COMMIT();
        }
        uint32_t* KHIw = (uint32_t*)(smc + ASTG + (kt & 1) * STG_SZ);
        uint32_t* KLOw = KHIw + 2304;
        uint32_t* VPw  = KHIw + 4608;

        // ---- S = Q K^T (16x64 per warp), 3-term fp16 split ----
        float S[8][4];
        #pragma unroll
        for (int n = 0; n < 8; n++)
            #pragma unroll
            for (int j = 0; j < 4; j++) S[n][j] = 0.f;
        #pragma unroll
        for (int ks = 0; ks < 4; ks++) {
            int a0w = (r0 + g) * 36 + 8 * ks + q;
            int a1w = (r0 + g + 8) * 36 + 8 * ks + q;
            uint32_t qh0 = QHIw[a0w],     qh1 = QHIw[a1w];
            uint32_t qh2 = QHIw[a0w + 4], qh3 = QHIw[a1w + 4];
            uint32_t ql0 = QLOw[a0w],     ql1 = QLOw[a1w];
            uint32_t ql2 = QLOw[a0w + 4], ql3 = QLOw[a1w + 4];
            #pragma unroll
            for (int n = 0; n < 8; n++) {
                int bw = (8 * n + g) * 36 + 8 * ks + q;
                uint32_t bh0 = KHIw[bw], bh1 = KHIw[bw + 4];
                uint32_t bl0 = KLOw[bw], bl1 = KLOw[bw + 4];
                mma16(S[n], qh0, qh1, qh2, qh3, bh0, bh1);
                mma16(S[n], qh0, qh1, qh2, qh3, bl0, bl1);
                mma16(S[n], ql0, ql1, ql2, ql3, bh0, bh1);
            }
        }

        // ---- mask (diagonal tiles only) ----
        if (kt >= 2 * qt) {
            #pragma unroll
            for (int n = 0; n < 8; n++) {
                int kc = kt * 64 + 8 * n + 2 * q;
                if (kc     > qrow0) S[n][0] = MASK_FILL;
                if (kc + 1 > qrow0) S[n][1] = MASK_FILL;
                if (kc     > qrow1) S[n][2] = MASK_FILL;
                if (kc + 1 > qrow1) S[n][3] = MASK_FILL;
            }
        }

        // ---- online max (coarse, per tile) ----
        float rm0 = -1e30f, rm1 = -1e30f;
        #pragma unroll
        for (int n = 0; n < 8; n++) {
            rm0 = fmaxf(rm0, fmaxf(S[n][0], S[n][1]));
            rm1 = fmaxf(rm1, fmaxf(S[n][2], S[n][3]));
        }
        rm0 = fmaxf(rm0, __shfl_xor_sync(~0u, rm0, 1));
        rm0 = fmaxf(rm0, __shfl_xor_sync(~0u, rm0, 2));
        rm1 = fmaxf(rm1, __shfl_xor_sync(~0u, rm1, 1));
        rm1 = fmaxf(rm1, __shfl_xor_sync(~0u, rm1, 2));
        float mn0 = fmaxf(m0, rm0), mn1 = fmaxf(m1, rm1);
        float sc0 = __expf(m0 - mn0), sc1 = __expf(m1 - mn1);
        m0 = mn0; m1 = mn1;
        ls0 *= sc0; ls1 *= sc1;
        #pragma unroll
        for (int n = 0; n < 8; n++) {
            O[n][0] *= sc0; O[n][1] *= sc0;
            O[n][2] *= sc1; O[n][3] *= sc1;
        }

        // ---- exp -> fp16 P (A-frags directly); l from rounded P ----
        uint32_t u01[8], u23[8];
        #pragma unroll
        for (int n = 0; n < 8; n++) {
            float p0 = __expf(S[n][0] - mn0), p1 = __expf(S[n][1] - mn0);
            float p2 = __expf(S[n][2] - mn1), p3 = __expf(S[n][3] - mn1);
            __half2 hp01 = __floats2half2_rn(p0, p1);
            __half2 hp23 = __floats2half2_rn(p2, p3);
            u01[n] = h2u(hp01); u23[n] = h2u(hp23);
            float2 f01 = __half22float2(hp01);
            float2 f23 = __half22float2(hp23);
            ls0 += f01.x + f01.y;
            ls1 += f23.x + f23.y;
        }

        // ---- O += P V ----
        #pragma unroll
        for (int kp = 0; kp < 4; kp++) {
            uint32_t a0 = u01[2*kp],     a1 = u23[2*kp];
            uint32_t a2 = u01[2*kp + 1], a3 = u23[2*kp + 1];
            #pragma unroll
            for (int n2 = 0; n2 < 8; n2++) {
                uint32_t b0 = VPw[(8*kp + q)     * 72 + 8*n2 + g];
                uint32_t b1 = VPw[(8*kp + q + 4) * 72 + 8*n2 + g];
                mma16(O[n2], a0, a1, a2, a3, b0, b1);
            }
        }
    }

    // ---- reduce l over quad, fold masked tail (rank-1), normalize, write --
    ls0 += __shfl_xor_sync(~0u, ls0, 1); ls0 += __shfl_xor_sync(~0u, ls0, 2);
    ls1 += __shfl_xor_sync(~0u, ls1, 1); ls1 += __shfl_xor_sync(~0u, ls1, 2);

    const float cntf = (float)(NSEQ - (qt + 1) * 128);
    const float e0 = __expf(MASK_FILL - m0);
    const float e1 = __expf(MASK_FILL - m1);
    const float inv0 = 1.0f / (ls0 + e0 * cntf);
    const float inv1 = 1.0f / (ls1 + e1 * cntf);
    const float* vs = &g_vsuf[((size_t)bh * (NT64 + 1) + (qt + 1) * 2) * DHEAD];

    #pragma unroll
    for (int n2 = 0; n2 < 8; n2++) {
        int col = 8 * n2 + 2 * q;
        float2 vv = *(const float2*)&vs[col];
        float o00 = (O[n2][0] + e0 * vv.x) * inv0;
        float o01 = (O[n2][1] + e0 * vv.y) * inv0;
        float o10 = (O[n2][2] + e1 * vv.x) * inv1;
        float o11 = (O[n2][3] + e1 * vv.y) * inv1;
        size_t ob0 = ((size_t)b * NSEQ + qrow0) * DIM + h * DHEAD + col;
        size_t ob1 = ((size_t)b * NSEQ + qrow1) * DIM + h * DHEAD + col;
        *(float2*)&out[ob0] = make_float2(o00, o01);
        *(float2*)&out[ob1] = make_float2(o10, o11);
    }
}

// ---------------- launch ----------------
extern "C" void kernel_launch(void* const* d_in, const int* in_sizes, int n_in,
                              void* d_out, int out_size) {
    const float* x     = (const float*)d_in[0];
    const float* gamma = (const float*)d_in[1];
    const float* beta  = (const float*)d_in[2];
    const float* w_qkv = (const float*)d_in[3];
    float* out = (float*)d_out;

    cudaFuncSetAttribute(qkv_gemm, cudaFuncAttributeMaxDynamicSharedMemorySize, GEMM_SMEM);
    cudaFuncSetAttribute(attn_kernel, cudaFuncAttributeMaxDynamicSharedMemorySize, ATTN_SMEM);

    ln_kernel<<<ROWS, 128>>>(x, gamma, beta);
    qkv_gemm<<<dim3(1536 / 64, ROWS / 128), 256, GEMM_SMEM>>>(w_qkv);
    vsuf_kernel<<<BH, 256>>>();
    attn_kernel<<<dim3(NQT, BH), 256, ATTN_SMEM>>>(out);
}